// round 4
// baseline (speedup 1.0000x reference)
#include <cuda_runtime.h>
#include <cstdint>
#include <cstddef>

#define EMB   768
#define HEADS 12
#define QKV   9216
#define FFD   3072
#define TOK   4096   /* B*T */
#define SEQ   2048

// ---------------- scratch (static device globals; no allocation) ----------------
__device__ float g_h  [(size_t)TOK*EMB];
__device__ float g_q  [(size_t)TOK*QKV];
__device__ float g_k  [(size_t)TOK*QKV];
__device__ float g_vt [(size_t)QKV*TOK];     // V^T: [9216][4096]
__device__ float g_s  [(size_t)2*HEADS*SEQ*SEQ];
__device__ float g_y  [(size_t)TOK*QKV];
__device__ float g_x2 [(size_t)TOK*EMB];
__device__ float g_ff [(size_t)TOK*FFD];
__device__ float g_wqt[(size_t)QKV*EMB];
__device__ float g_wkt[(size_t)QKV*EMB];
__device__ float g_wvt[(size_t)QKV*EMB];
__device__ float g_wot[(size_t)EMB*QKV];
__device__ float g_w1t[(size_t)FFD*EMB];
__device__ float g_w2t[(size_t)EMB*FFD];

// ---------------- helpers ----------------
__device__ __forceinline__ uint32_t f2tf(float x){
    uint32_t r; asm("cvt.rna.tf32.f32 %0, %1;" : "=r"(r) : "f"(x)); return r;
}
__device__ __forceinline__ float rnd(float x){ return __uint_as_float(f2tf(x)); }

__device__ __forceinline__ uint32_t smem_u32(const void* p){
    uint32_t a;
    asm("{ .reg .u64 t; cvta.to.shared.u64 t, %1; cvt.u32.u64 %0, t; }" : "=r"(a) : "l"(p));
    return a;
}
__device__ __forceinline__ void cp16(uint32_t sdst, const void* gsrc){
    asm volatile("cp.async.cg.shared.global [%0], [%1], 16;" :: "r"(sdst), "l"(gsrc));
}
__device__ __forceinline__ void cp_commit(){ asm volatile("cp.async.commit_group;"); }
__device__ __forceinline__ void cp_wait0(){ asm volatile("cp.async.wait_group 0;"); }
__device__ __forceinline__ void cp_wait1(){ asm volatile("cp.async.wait_group 1;"); }

__device__ __forceinline__ void mma8(float* d, const uint32_t* a, const uint32_t* b){
    asm volatile(
      "mma.sync.aligned.m16n8k8.row.col.f32.tf32.tf32.f32 "
      "{%0,%1,%2,%3},{%4,%5,%6,%7},{%8,%9},{%0,%1,%2,%3};"
      : "+f"(d[0]), "+f"(d[1]), "+f"(d[2]), "+f"(d[3])
      : "r"(a[0]), "r"(a[1]), "r"(a[2]), "r"(a[3]), "r"(b[0]), "r"(b[1]));
}
__device__ __forceinline__ float gelu_f(float x){ return x * normcdff(x); }

// byte-offset swizzle for 128B rows, 16B granules: granule ^= (row & 7)
#define SWZ(x) ((x) ^ (((x) >> 3) & 0x70))

// ---------------- tcgen-free NT GEMM (tf32 mma.sync, SW128 smem, LDS.64 frags) ----------------
// C[M,N] = A[M,K] @ B^T, B stored [N,K] K-major. All operands pre-rounded to tf32.
// EPI: 0 none, 1 bias+resid, 2 bias+gelu
// RND: round outputs to tf32 (for operands of later GEMMs)
// CAUSAL: 0 none, 1 skip tiles n0>=m0+128 (scores), 2 K-limit to m0+128 (P@V)
#define BM 128
#define BN 128
#define BK 32
#define GT 256
#define TILE_BYTES 16384            /* 128 rows x 128B */
#define SMEM_TOT   65536            /* A0 A1 B0 B1 */

template<int EPI, bool RND, int CAUSAL>
__global__ __launch_bounds__(GT, 2)
void gemm_nt(const float* __restrict__ A, const float* __restrict__ B, float* __restrict__ C,
             int K, int lda, int ldb, int ldc,
             long long sA1, long long sA2, long long sB1, long long sB2,
             long long sC1, long long sC2, int zdiv,
             const float* __restrict__ bias, const float* __restrict__ resid, int ldr)
{
    const int m0 = blockIdx.y * BM;
    const int n0 = blockIdx.x * BN;
    if (CAUSAL == 1 && n0 >= m0 + BM) return;

    const int z  = blockIdx.z;
    const int zb = z / zdiv, zh = z - zb*zdiv;
    A += zb*sA1 + zh*sA2 + (size_t)m0*lda;
    B += zb*sB1 + zh*sB2 + (size_t)n0*ldb;
    C += zb*sC1 + zh*sC2 + (size_t)m0*ldc + n0;
    if (EPI >= 1) bias  += n0;
    if (EPI == 1) resid += (size_t)m0*ldr + n0;

    int Keff = K;
    if (CAUSAL == 2){ int kl = m0 + BM; Keff = kl < K ? kl : K; }
    const int nk = Keff / BK;

    extern __shared__ char smem[];
    const uint32_t sb = smem_u32(smem);
    const int t    = threadIdx.x;
    const int lane = t & 31;
    const int warp = t >> 5;
    const int wm   = warp & 1;      // 2 warps in M
    const int wn   = warp >> 1;     // 4 warps in N
    const int rb   = wm*64 + (lane >> 2);
    const int cb   = wn*32 + (lane >> 2);
    const int kq   = lane & 3;

    auto copy_tile = [&](int kt, int p){
        const int k0 = kt * BK;
        const uint32_t Ab = sb + p*TILE_BYTES;
        const uint32_t Bb = sb + 2*TILE_BYTES + p*TILE_BYTES;
        #pragma unroll
        for (int i = 0; i < 4; ++i){
            int e = t + i*GT; int r = e >> 3, g = e & 7;
            cp16(Ab + SWZ(r*128 + g*16), A + (size_t)r*lda + k0 + g*4);
        }
        #pragma unroll
        for (int i = 0; i < 4; ++i){
            int e = t + i*GT; int r = e >> 3, g = e & 7;
            cp16(Bb + SWZ(r*128 + g*16), B + (size_t)r*ldb + k0 + g*4);
        }
    };

    float acc[4][4][4];
    #pragma unroll
    for (int mt=0; mt<4; mt++)
        #pragma unroll
        for (int nt=0; nt<4; nt++)
            #pragma unroll
            for (int i=0;i<4;i++) acc[mt][nt][i]=0.f;

    copy_tile(0, 0); cp_commit();

    for (int it = 0; it < nk; ++it){
        const int p = it & 1;
        if (it + 1 < nk){ copy_tile(it+1, p^1); cp_commit(); cp_wait1(); }
        else            { cp_wait0(); }
        __syncthreads();
        const char* Ab = smem + p*TILE_BYTES;
        const char* Bb = smem + 2*TILE_BYTES + p*TILE_BYTES;
        #pragma unroll
        for (int s4 = 0; s4 < 4; ++s4){
            const int cbyte = 32*s4 + 8*kq;          // float2 covering mma-k kq, kq+4
            uint32_t af[4][4];
            #pragma unroll
            for (int mt=0; mt<4; mt++){
                const int r = rb + mt*16;
                float2 v1 = *(const float2*)(Ab + SWZ( r   *128 + cbyte));
                float2 v2 = *(const float2*)(Ab + SWZ((r+8)*128 + cbyte));
                af[mt][0] = __float_as_uint(v1.x);
                af[mt][1] = __float_as_uint(v2.x);
                af[mt][2] = __float_as_uint(v1.y);
                af[mt][3] = __float_as_uint(v2.y);
            }
            uint32_t bf[4][2];
            #pragma unroll
            for (int nt=0; nt<4; nt++){
                const int c = cb + nt*8;
                float2 w = *(const float2*)(Bb + SWZ(c*128 + cbyte));
                bf[nt][0] = __float_as_uint(w.x);
                bf[nt][1] = __float_as_uint(w.y);
            }
            #pragma unroll
            for (int mt=0; mt<4; mt++)
                #pragma unroll
                for (int nt=0; nt<4; nt++)
                    mma8(acc[mt][nt], af[mt], bf[nt]);
        }
        __syncthreads();
    }

    // epilogue
    const int ce = (lane & 3) * 2;
    #pragma unroll
    for (int mt=0; mt<4; mt++){
        const int r0 = wm*64 + mt*16 + (lane>>2);
        #pragma unroll
        for (int nt=0; nt<4; nt++){
            const int c = wn*32 + nt*8 + ce;
            float v0=acc[mt][nt][0], v1=acc[mt][nt][1], v2=acc[mt][nt][2], v3=acc[mt][nt][3];
            if (EPI >= 1){
                float bb0 = bias[c], bb1 = bias[c+1];
                v0+=bb0; v1+=bb1; v2+=bb0; v3+=bb1;
            }
            if (EPI == 1){
                v0 += resid[(size_t) r0   *ldr + c    ];
                v1 += resid[(size_t) r0   *ldr + c + 1];
                v2 += resid[(size_t)(r0+8)*ldr + c    ];
                v3 += resid[(size_t)(r0+8)*ldr + c + 1];
            }
            if (EPI == 2){ v0=gelu_f(v0); v1=gelu_f(v1); v2=gelu_f(v2); v3=gelu_f(v3); }
            if (RND){ v0=rnd(v0); v1=rnd(v1); v2=rnd(v2); v3=rnd(v3); }
            *(float2*)(C + (size_t) r0   *ldc + c) = make_float2(v0,v1);
            *(float2*)(C + (size_t)(r0+8)*ldc + c) = make_float2(v2,v3);
        }
    }
}

// ---------------- transpose + tf32 round (dst[C][R] = round(src[R][C]^T)) ----------------
__global__ __launch_bounds__(256)
void transpose_k(const float* __restrict__ src, float* __restrict__ dst, int R, int C)
{
    __shared__ float tile[32][33];
    const int bx = blockIdx.x*32, by = blockIdx.y*32;
    const int tx = threadIdx.x, ty = threadIdx.y;   // (32,8)
    #pragma unroll
    for (int j = 0; j < 32; j += 8)
        tile[ty+j][tx] = src[(size_t)(by+ty+j)*C + bx+tx];
    __syncthreads();
    #pragma unroll
    for (int j = 0; j < 32; j += 8)
        dst[(size_t)(bx+ty+j)*R + by+tx] = rnd(tile[tx][ty+j]);
}

// ---------------- LayerNorm (outputs tf32-rounded) ----------------
__global__ __launch_bounds__(256)
void ln_kernel(const float* __restrict__ x, const float* __restrict__ g,
               const float* __restrict__ b, float* __restrict__ o)
{
    __shared__ float sh[16];
    const int row = blockIdx.x;
    const float* xr = x + (size_t)row*EMB;
    const int t = threadIdx.x;
    float v0 = xr[t], v1 = xr[t+256], v2 = xr[t+512];
    float s  = v0+v1+v2;
    float s2 = v0*v0 + v1*v1 + v2*v2;
    #pragma unroll
    for (int off=16; off; off>>=1){
        s  += __shfl_down_sync(0xffffffffu, s,  off);
        s2 += __shfl_down_sync(0xffffffffu, s2, off);
    }
    const int lane = t&31, wid = t>>5;
    if (lane==0){ sh[wid]=s; sh[8+wid]=s2; }
    __syncthreads();
    if (t==0){
        float a=0.f, c=0.f;
        #pragma unroll
        for (int i=0;i<8;i++){ a+=sh[i]; c+=sh[8+i]; }
        sh[0]=a; sh[8]=c;
    }
    __syncthreads();
    const float mu  = sh[0]*(1.f/EMB);
    const float var = sh[8]*(1.f/EMB) - mu*mu;
    const float rs  = rsqrtf(var + 1e-5f);
    float* orow = o + (size_t)row*EMB;
    orow[t]     = rnd((v0-mu)*rs*g[t]     + b[t]);
    orow[t+256] = rnd((v1-mu)*rs*g[t+256] + b[t+256]);
    orow[t+512] = rnd((v2-mu)*rs*g[t+512] + b[t+512]);
}

// ---------------- causal softmax (scale, mask, normalize, tf32-round) ----------------
// Touches only cols [0, Lb), Lb = 128-aligned causal extent; zeroes [L, Lb).
__global__ __launch_bounds__(256)
void softmax_kernel(float* __restrict__ S)
{
    __shared__ float shm[8];
    __shared__ float shs[8];
    const int i = blockIdx.x;
    const long long z = blockIdx.y;
    float* row = S + (z*(long long)SEQ + i) * (long long)SEQ;
    const int L  = i + 1;
    const int Lb = ((i >> 7) + 1) << 7;
    const int t = threadIdx.x;
    const int lane = t & 31, wid = t >> 5;
    const float scale = 1.0f/96.0f;   // 1/sqrt(9216)

    float4 v[2];
    float mx = -1e30f;
    #pragma unroll
    for (int u=0; u<2; u++){
        int j = (t + (u<<8)) << 2;
        if (j < Lb){
            float4 w = *(float4*)(row + j);
            w.x = (j   < L) ? w.x*scale : -1e30f;
            w.y = (j+1 < L) ? w.y*scale : -1e30f;
            w.z = (j+2 < L) ? w.z*scale : -1e30f;
            w.w = (j+3 < L) ? w.w*scale : -1e30f;
            v[u] = w;
            mx = fmaxf(mx, fmaxf(fmaxf(w.x,w.y), fmaxf(w.z,w.w)));
        } else {
            v[u] = make_float4(-1e30f,-1e30f,-1e30f,-1e30f);
        }
    }
    #pragma unroll
    for (int o=16; o; o>>=1) mx = fmaxf(mx, __shfl_xor_sync(0xffffffffu, mx, o));
    if (lane==0) shm[wid] = mx;
    __syncthreads();
    float m = shm[0];
    #pragma unroll
    for (int w=1; w<8; w++) m = fmaxf(m, shm[w]);

    float sum = 0.f;
    #pragma unroll
    for (int u=0; u<2; u++){
        v[u].x = __expf(v[u].x - m);
        v[u].y = __expf(v[u].y - m);
        v[u].z = __expf(v[u].z - m);
        v[u].w = __expf(v[u].w - m);
        sum += v[u].x + v[u].y + v[u].z + v[u].w;
    }
    #pragma unroll
    for (int o=16; o; o>>=1) sum += __shfl_xor_sync(0xffffffffu, sum, o);
    if (lane==0) shs[wid] = sum;
    __syncthreads();
    float tot = 0.f;
    #pragma unroll
    for (int w=0; w<8; w++) tot += shs[w];
    const float inv = 1.0f / tot;
    #pragma unroll
    for (int u=0; u<2; u++){
        int j = (t + (u<<8)) << 2;
        if (j < Lb){
            float4 w = v[u];
            w.x = rnd(w.x*inv); w.y = rnd(w.y*inv);
            w.z = rnd(w.z*inv); w.w = rnd(w.w*inv);
            *(float4*)(row + j) = w;
        }
    }
}

// ---------------- launch ----------------
extern "C" void kernel_launch(void* const* d_in, const int* in_sizes, int n_in,
                              void* d_out, int out_size)
{
    const float* x   = (const float*)d_in[0];
    const float* Wq  = (const float*)d_in[1];
    const float* Wk  = (const float*)d_in[2];
    const float* Wv  = (const float*)d_in[3];
    const float* Wo  = (const float*)d_in[4];
    const float* bo  = (const float*)d_in[5];
    const float* W1  = (const float*)d_in[6];
    const float* b1  = (const float*)d_in[7];
    const float* W2  = (const float*)d_in[8];
    const float* b2  = (const float*)d_in[9];
    const float* g1  = (const float*)d_in[10];
    const float* be1 = (const float*)d_in[11];
    const float* g2  = (const float*)d_in[12];
    const float* be2 = (const float*)d_in[13];
    float* out = (float*)d_out;

    float *h,*q,*k,*vt,*s,*y,*x2,*ff,*wqt,*wkt,*wvt,*wot,*w1t,*w2t;
    cudaGetSymbolAddress((void**)&h,   g_h);
    cudaGetSymbolAddress((void**)&q,   g_q);
    cudaGetSymbolAddress((void**)&k,   g_k);
    cudaGetSymbolAddress((void**)&vt,  g_vt);
    cudaGetSymbolAddress((void**)&s,   g_s);
    cudaGetSymbolAddress((void**)&y,   g_y);
    cudaGetSymbolAddress((void**)&x2,  g_x2);
    cudaGetSymbolAddress((void**)&ff,  g_ff);
    cudaGetSymbolAddress((void**)&wqt, g_wqt);
    cudaGetSymbolAddress((void**)&wkt, g_wkt);
    cudaGetSymbolAddress((void**)&wvt, g_wvt);
    cudaGetSymbolAddress((void**)&wot, g_wot);
    cudaGetSymbolAddress((void**)&w1t, g_w1t);
    cudaGetSymbolAddress((void**)&w2t, g_w2t);

    static bool attr_done = false;
    if (!attr_done){
        cudaFuncSetAttribute(gemm_nt<0,true ,0>, cudaFuncAttributeMaxDynamicSharedMemorySize, SMEM_TOT);
        cudaFuncSetAttribute(gemm_nt<0,false,1>, cudaFuncAttributeMaxDynamicSharedMemorySize, SMEM_TOT);
        cudaFuncSetAttribute(gemm_nt<0,true ,2>, cudaFuncAttributeMaxDynamicSharedMemorySize, SMEM_TOT);
        cudaFuncSetAttribute(gemm_nt<1,false,0>, cudaFuncAttributeMaxDynamicSharedMemorySize, SMEM_TOT);
        cudaFuncSetAttribute(gemm_nt<2,true ,0>, cudaFuncAttributeMaxDynamicSharedMemorySize, SMEM_TOT);
        attr_done = true;
    }

    dim3 tb(32, 8);
    // weight transposes + tf32 rounding (NT operand layout)
    transpose_k<<<dim3(QKV/32, EMB/32), tb>>>(Wq, wqt, EMB, QKV);
    transpose_k<<<dim3(QKV/32, EMB/32), tb>>>(Wk, wkt, EMB, QKV);
    transpose_k<<<dim3(QKV/32, EMB/32), tb>>>(Wv, wvt, EMB, QKV);
    transpose_k<<<dim3(EMB/32, QKV/32), tb>>>(Wo, wot, QKV, EMB);
    transpose_k<<<dim3(FFD/32, EMB/32), tb>>>(W1, w1t, EMB, FFD);
    transpose_k<<<dim3(EMB/32, FFD/32), tb>>>(W2, w2t, FFD, EMB);

    // h = round(LN1(x))
    ln_kernel<<<TOK,256>>>(x, g1, be1, h);

    // q = h @ Wq, k = h @ Wk  (NT: B = W^T [9216,768]); outputs rounded
    gemm_nt<0,true,0><<<dim3(QKV/BN, TOK/BM, 1), GT, SMEM_TOT>>>(
        h, wqt, q, EMB, EMB, EMB, QKV, 0,0,0,0,0,0, 1, nullptr, nullptr, 0);
    gemm_nt<0,true,0><<<dim3(QKV/BN, TOK/BM, 1), GT, SMEM_TOT>>>(
        h, wkt, k, EMB, EMB, EMB, QKV, 0,0,0,0,0,0, 1, nullptr, nullptr, 0);

    // vt = WvT @ h^T -> [9216,4096]  (NT: A=WvT, B=h); output rounded
    gemm_nt<0,true,0><<<dim3(TOK/BN, QKV/BM, 1), GT, SMEM_TOT>>>(
        wvt, h, vt, EMB, EMB, EMB, TOK, 0,0,0,0,0,0, 1, nullptr, nullptr, 0);

    // scores[z] = Q_z @ K_z^T  (causal tile skip; no rounding — softmax rounds)
    gemm_nt<0,false,1><<<dim3(SEQ/BN, SEQ/BM, 2*HEADS), GT, SMEM_TOT>>>(
        q, k, s, EMB, QKV, QKV, SEQ,
        (long long)SEQ*QKV, (long long)EMB,
        (long long)SEQ*QKV, (long long)EMB,
        (long long)HEADS*SEQ*SEQ, (long long)SEQ*SEQ, HEADS,
        nullptr, nullptr, 0);

    // causal softmax (scale + mask + normalize + round; zeroes masked cols to block edge)
    softmax_kernel<<<dim3(SEQ, 2*HEADS),256>>>(s);

    // y[z] = P_z @ V_z  (NT: B = vt slice [d][s]; K limited to causal extent); rounded
    gemm_nt<0,true,2><<<dim3(EMB/BN, SEQ/BM, 2*HEADS), GT, SMEM_TOT>>>(
        s, vt, y, SEQ, SEQ, TOK, QKV,
        (long long)HEADS*SEQ*SEQ, (long long)SEQ*SEQ,
        (long long)SEQ, (long long)EMB*TOK,
        (long long)SEQ*QKV, (long long)EMB, HEADS,
        nullptr, nullptr, 0);

    // x2 = y @ Wo + bo + x  (exact f32 out)
    gemm_nt<1,false,0><<<dim3(EMB/BN, TOK/BM, 1), GT, SMEM_TOT>>>(
        y, wot, x2, QKV, QKV, QKV, EMB, 0,0,0,0,0,0, 1, bo, x, EMB);

    // h = round(LN2(x2))
    ln_kernel<<<TOK,256>>>(x2, g2, be2, h);

    // ff = round(gelu(h @ W1 + b1))
    gemm_nt<2,true,0><<<dim3(FFD/BN, TOK/BM, 1), GT, SMEM_TOT>>>(
        h, w1t, ff, EMB, EMB, EMB, FFD, 0,0,0,0,0,0, 1, b1, nullptr, 0);

    // out = ff @ W2 + b2 + x2  (exact f32 out)
    gemm_nt<1,false,0><<<dim3(EMB/BN, TOK/BM, 1), GT, SMEM_TOT>>>(
        ff, w2t, out, FFD, FFD, FFD, EMB, 0,0,0,0,0,0, 1, b2, x2, EMB);
}